// round 12
// baseline (speedup 1.0000x reference)
#include <cuda_runtime.h>
#include <cuda_bf16.h>
#include <math.h>
#include <stdint.h>

// ---------------------------------------------------------------------------
// GAT 3-layer fused pipeline for GB300 — round 9: 3xTF32 tensor-core GEMM.
// d_out layout (fp32): out[N*64] | alpha1[E*4] | alpha2[E*4] | alpha3[E*4]
// ---------------------------------------------------------------------------

#define MAX_N 50000
#define MAX_E 1600000

__device__ float g_feat[(size_t)MAX_N * 256];
__device__ float g_skip[(size_t)MAX_N * 128];
__device__ float g_xin [(size_t)MAX_N * 128];
__device__ float g_as  [(size_t)MAX_N * 4];
__device__ float g_ad  [(size_t)MAX_N * 4];
__device__ float g_inv [(size_t)MAX_N * 4];
__device__ float g_ex  [(size_t)MAX_E * 4];
__device__ int   g_src [MAX_E];
__device__ int   g_dst [MAX_E];
__device__ int   g_csr [MAX_E];
__device__ int   g_rowstart[MAX_N + 1];
__device__ int   g_deg   [MAX_N];
__device__ int   g_cursor[MAX_N];
__device__ int   g_scan  [MAX_N];
__device__ int   g_bsum  [64];
__device__ int   g_is64;

// ---------------------------------------------------------------------------
// Edge-index dtype sniffing + conversion to int32 (+ per-dst degree count)
// ---------------------------------------------------------------------------
__global__ void detect_idx_kernel(const long long* __restrict__ ei, int n_nodes) {
    if (threadIdx.x == 0 && blockIdx.x == 0) {
        int ok = 1;
        for (int i = 0; i < 16; i++) {
            long long v = ei[i];
            if (v < 0 || v >= (long long)n_nodes) { ok = 0; break; }
        }
        g_is64 = ok;
    }
}

__global__ void zero_deg_kernel(int n) {
    int i = blockIdx.x * blockDim.x + threadIdx.x;
    if (i < n) g_deg[i] = 0;
}

__global__ void convert_idx_kernel(const void* __restrict__ ei, int E) {
    int i = blockIdx.x * blockDim.x + threadIdx.x;
    if (i >= E) return;
    int s, d;
    if (g_is64) {
        const long long* p = (const long long*)ei;
        s = (int)p[i];
        d = (int)p[(size_t)E + i];
    } else {
        const int* p = (const int*)ei;
        s = p[i];
        d = p[E + i];
    }
    g_src[i] = s;
    g_dst[i] = d;
    atomicAdd(&g_deg[d], 1);
}

// ---------------------------------------------------------------------------
// Parallel 3-phase exclusive scan of g_deg -> g_rowstart / g_cursor
// ---------------------------------------------------------------------------
__global__ __launch_bounds__(1024)
void scan1_kernel(int n) {
    int i = blockIdx.x * 1024 + threadIdx.x;
    int lane = threadIdx.x & 31, wid = threadIdx.x >> 5;
    int v = (i < n) ? g_deg[i] : 0;
    int x = v;
#pragma unroll
    for (int o = 1; o < 32; o <<= 1) {
        int t = __shfl_up_sync(0xffffffffu, x, o);
        if (lane >= o) x += t;
    }
    __shared__ int ws[32];
    if (lane == 31) ws[wid] = x;
    __syncthreads();
    if (wid == 0) {
        int y = ws[lane];
#pragma unroll
        for (int o = 1; o < 32; o <<= 1) {
            int t = __shfl_up_sync(0xffffffffu, y, o);
            if (lane >= o) y += t;
        }
        ws[lane] = y;
    }
    __syncthreads();
    int incl = x + (wid ? ws[wid - 1] : 0);
    if (i < n) g_scan[i] = incl;
    if (threadIdx.x == 1023) g_bsum[blockIdx.x] = incl;
}

__global__ void scan2_kernel(int nb) {   // <<<1, 64>>>; nb <= 64
    int tid = threadIdx.x;
    int lane = tid & 31, wid = tid >> 5;
    int v = (tid < nb) ? g_bsum[tid] : 0;
    int x = v;
#pragma unroll
    for (int o = 1; o < 32; o <<= 1) {
        int t = __shfl_up_sync(0xffffffffu, x, o);
        if (lane >= o) x += t;
    }
    __shared__ int w0;
    if (wid == 0 && lane == 31) w0 = x;
    __syncthreads();
    if (wid == 1) x += w0;
    if (tid < nb) g_bsum[tid] = x;
}

__global__ void scan3_kernel(int n, int nb) {
    int i = blockIdx.x * blockDim.x + threadIdx.x;
    if (i > n) return;
    if (i == n) {
        g_rowstart[n] = g_bsum[nb - 1];
        return;
    }
    int blk = i >> 10;
    int excl = g_scan[i] - g_deg[i] + (blk ? g_bsum[blk - 1] : 0);
    g_rowstart[i] = excl;
    g_cursor[i]   = excl;
}

__global__ void scatter_kernel(int E) {
    int i = blockIdx.x * blockDim.x + threadIdx.x;
    if (i >= E) return;
    int d = g_dst[i];
    int pos = atomicAdd(&g_cursor[d], 1);
    g_csr[pos] = g_src[i];
}

// ---------------------------------------------------------------------------
// 3xTF32 tensor-core GEMM: C[n,m] = sum_k A[n,k] * B[k,m]
// BM=128, BN=64, BK=32, 256 threads = 8 warps (4x2), warp tile 32x32.
// mma.sync.m16n8k8.tf32; 3 passes (hi*hi + hi*lo + lo*hi) -> ~fp32 accuracy.
// K multiple of 32, M multiple of 64.
// ---------------------------------------------------------------------------
__device__ __forceinline__ uint32_t f2tf(float x) {
    uint32_t r;
    asm("cvt.rna.tf32.f32 %0, %1;" : "=r"(r) : "f"(x));
    return r;
}

__device__ __forceinline__ void mma_tf32(float c[4], uint32_t a0, uint32_t a1,
                                         uint32_t a2, uint32_t a3,
                                         uint32_t b0, uint32_t b1) {
    asm volatile(
        "mma.sync.aligned.m16n8k8.row.col.f32.tf32.tf32.f32 "
        "{%0,%1,%2,%3}, {%4,%5,%6,%7}, {%8,%9}, {%0,%1,%2,%3};"
        : "+f"(c[0]), "+f"(c[1]), "+f"(c[2]), "+f"(c[3])
        : "r"(a0), "r"(a1), "r"(a2), "r"(a3), "r"(b0), "r"(b1));
}

__global__ __launch_bounds__(256)
void gemm_tf32_kernel(const float* __restrict__ A, const float* __restrict__ B,
                      float* __restrict__ C, int nRows, int K, int M) {
    __shared__ float As[32][136];   // [k][row], padded
    __shared__ float Bs[32][64];    // [k][col]

    int tid  = threadIdx.x;
    int wid  = tid >> 5;
    int lane = tid & 31;
    int g    = lane >> 2;           // groupID 0..7
    int tg   = lane & 3;            // thread-in-group 0..3
    int wm   = wid >> 1;            // 0..3  (32-row slab)
    int wn   = wid & 1;             // 0..1  (32-col slab)
    int row0 = blockIdx.y * 128, col0 = blockIdx.x * 64;

    float c[2][4][4];               // [m-tile][n-tile][frag]
#pragma unroll
    for (int mt = 0; mt < 2; mt++)
#pragma unroll
        for (int nt = 0; nt < 4; nt++)
#pragma unroll
            for (int q = 0; q < 4; q++) c[mt][nt][q] = 0.f;

    for (int k0 = 0; k0 < K; k0 += 32) {
        // A tile: 128 rows x 32 cols = 1024 float4 over 256 threads (4 each)
#pragma unroll
        for (int t = 0; t < 4; t++) {
            int f = tid + t * 256;
            int ar = f >> 3;            // 0..127
            int ac = (f & 7) << 2;      // 0..28
            int grow = row0 + ar;
            float4 v = make_float4(0.f, 0.f, 0.f, 0.f);
            if (grow < nRows)
                v = *(const float4*)(A + (size_t)grow * K + k0 + ac);
            As[ac + 0][ar] = v.x; As[ac + 1][ar] = v.y;
            As[ac + 2][ar] = v.z; As[ac + 3][ar] = v.w;
        }
        // B tile: 32 rows x 64 cols = 512 float4 (2 each)
#pragma unroll
        for (int t = 0; t < 2; t++) {
            int f = tid + t * 256;
            int br = f >> 4;            // 0..31
            int bc = (f & 15) << 2;     // 0..60
            *(float4*)&Bs[br][bc] =
                *(const float4*)(B + (size_t)(k0 + br) * M + col0 + bc);
        }
        __syncthreads();

#pragma unroll
        for (int ks = 0; ks < 32; ks += 8) {
            // --- A fragments: 2 m-tiles, 4 regs each ---
            uint32_t ahi[2][4], alo[2][4];
#pragma unroll
            for (int mt = 0; mt < 2; mt++) {
                int rm = wm * 32 + mt * 16;
                float a0 = As[ks + tg][rm + g];
                float a1 = As[ks + tg][rm + g + 8];
                float a2 = As[ks + tg + 4][rm + g];
                float a3 = As[ks + tg + 4][rm + g + 8];
                ahi[mt][0] = f2tf(a0); alo[mt][0] = f2tf(a0 - __uint_as_float(ahi[mt][0]));
                ahi[mt][1] = f2tf(a1); alo[mt][1] = f2tf(a1 - __uint_as_float(ahi[mt][1]));
                ahi[mt][2] = f2tf(a2); alo[mt][2] = f2tf(a2 - __uint_as_float(ahi[mt][2]));
                ahi[mt][3] = f2tf(a3); alo[mt][3] = f2tf(a3 - __uint_as_float(ahi[mt][3]));
            }
            // --- B fragments: 4 n-tiles, 2 regs each ---
            uint32_t bhi[4][2], blo[4][2];
#pragma unroll
            for (int nt = 0; nt < 4; nt++) {
                int cn = wn * 32 + nt * 8;
                float b0 = Bs[ks + tg][cn + g];
                float b1 = Bs[ks + tg + 4][cn + g];
                bhi[nt][0] = f2tf(b0); blo[nt][0] = f2tf(b0 - __uint_as_float(bhi[nt][0]));
                bhi[nt][1] = f2tf(b1); blo[nt][1] = f2tf(b1 - __uint_as_float(bhi[nt][1]));
            }
            // --- 3-pass MMAs ---
#pragma unroll
            for (int mt = 0; mt < 2; mt++)
#pragma unroll
                for (int nt = 0; nt < 4; nt++) {
                    mma_tf32(c[mt][nt], ahi[mt][0], ahi[mt][1], ahi[mt][2], ahi[mt][3],
                             bhi[nt][0], bhi[nt][1]);
                    mma_tf32(c[mt][nt], ahi[mt][0], ahi[mt][1], ahi[mt][2], ahi[mt][3],
                             blo[nt][0], blo[nt][1]);
                    mma_tf32(c[mt][nt], alo[mt][0], alo[mt][1], alo[mt][2], alo[mt][3],
                             bhi[nt][0], bhi[nt][1]);
                }
        }
        __syncthreads();
    }

    // Store: c[mt][nt] -> rows row0+wm*32+mt*16+{g, g+8}, cols col0+wn*32+nt*8+2*tg
#pragma unroll
    for (int mt = 0; mt < 2; mt++) {
        int r0 = row0 + wm * 32 + mt * 16 + g;
        int r1 = r0 + 8;
#pragma unroll
        for (int nt = 0; nt < 4; nt++) {
            int cc = col0 + wn * 32 + nt * 8 + 2 * tg;
            if (r0 < nRows)
                *(float2*)(C + (size_t)r0 * M + cc) = make_float2(c[mt][nt][0], c[mt][nt][1]);
            if (r1 < nRows)
                *(float2*)(C + (size_t)r1 * M + cc) = make_float2(c[mt][nt][2], c[mt][nt][3]);
        }
    }
}

// ---------------------------------------------------------------------------
// as_[n,h] = sum_c h[n,h,c]*a_src[h,c]; ad_ likewise. One warp per (n,h).
// ---------------------------------------------------------------------------
__global__ __launch_bounds__(256)
void attn_coef_kernel(const float* __restrict__ feat,
                      const float* __restrict__ a_src, const float* __restrict__ a_dst,
                      float* __restrict__ as_, float* __restrict__ ad_,
                      int n, int C) {
    int w = (blockIdx.x * blockDim.x + threadIdx.x) >> 5;
    int lane = threadIdx.x & 31;
    if (w >= n * 4) return;
    int node = w >> 2, h = w & 3;
    const float* fp = feat + (size_t)node * 4 * C + h * C;
    float s1 = 0.f, s2 = 0.f;
    for (int c = lane; c < C; c += 32) {
        float v = fp[c];
        s1 += v * a_src[h * C + c];
        s2 += v * a_dst[h * C + c];
    }
#pragma unroll
    for (int o = 16; o; o >>= 1) {
        s1 += __shfl_xor_sync(0xffffffffu, s1, o);
        s2 += __shfl_xor_sync(0xffffffffu, s2, o);
    }
    if (lane == 0) { as_[w] = s1; ad_[w] = s2; }
}

// ---------------------------------------------------------------------------
// Fused per-destination edge kernel (warp per dst node), atomic-free.
// ---------------------------------------------------------------------------
template <int C, int MODE>
__global__ __launch_bounds__(256)
void gat_edge_kernel(const float* __restrict__ feat,
                     const float* __restrict__ as_,
                     const float* __restrict__ ad_,
                     float* __restrict__ inv_out,
                     float* __restrict__ xout,
                     const float* __restrict__ bias,
                     const float* __restrict__ lnw,
                     const float* __restrict__ lnb,
                     const float* __restrict__ skip,
                     const float* __restrict__ bskip,
                     int n) {
    constexpr int M  = 4 * C;
    constexpr int NR = M / 128;
    int w = (blockIdx.x * blockDim.x + threadIdx.x) >> 5;
    int lane = threadIdx.x & 31;
    if (w >= n) return;
    int start = g_rowstart[w];
    int end   = g_rowstart[w + 1];

    float4 adv = *(const float4*)(ad_ + 4 * (size_t)w);

    // ---- Loop A: ex + denominator partials ----
    float d0 = 0.f, d1 = 0.f, d2 = 0.f, d3 = 0.f;
    for (int i = start + lane; i < end; i += 32) {
        int sidx = g_csr[i];
        float4 av = *(const float4*)(as_ + 4 * (size_t)sidx);
        float e0 = av.x + adv.x; e0 = (e0 > 0.f) ? e0 : 0.2f * e0;
        float e1 = av.y + adv.y; e1 = (e1 > 0.f) ? e1 : 0.2f * e1;
        float e2 = av.z + adv.z; e2 = (e2 > 0.f) ? e2 : 0.2f * e2;
        float e3 = av.w + adv.w; e3 = (e3 > 0.f) ? e3 : 0.2f * e3;
        float x0 = __expf(e0), x1 = __expf(e1), x2 = __expf(e2), x3 = __expf(e3);
        *(float4*)(g_ex + (size_t)i * 4) = make_float4(x0, x1, x2, x3);
        d0 += x0; d1 += x1; d2 += x2; d3 += x3;
    }
    __syncwarp();
#pragma unroll
    for (int o = 16; o; o >>= 1) {
        d0 += __shfl_xor_sync(0xffffffffu, d0, o);
        d1 += __shfl_xor_sync(0xffffffffu, d1, o);
        d2 += __shfl_xor_sync(0xffffffffu, d2, o);
        d3 += __shfl_xor_sync(0xffffffffu, d3, o);
    }
    float i0 = 1.f / (d0 + 1e-16f);
    float i1 = 1.f / (d1 + 1e-16f);
    float i2 = 1.f / (d2 + 1e-16f);
    float i3 = 1.f / (d3 + 1e-16f);
    if (lane == 0)
        *(float4*)(inv_out + 4 * (size_t)w) = make_float4(i0, i1, i2, i3);

    // ---- Loop C: register-accumulated aggregation ----
    float4 acc[NR];
#pragma unroll
    for (int r = 0; r < NR; r++) acc[r] = make_float4(0.f, 0.f, 0.f, 0.f);

#pragma unroll 2
    for (int i = start; i < end; i++) {
        int sidx = g_csr[i];
        float4 ex = *(const float4*)(g_ex + (size_t)i * 4);
        const float4* fp = (const float4*)(feat + (size_t)sidx * M);
#pragma unroll
        for (int r = 0; r < NR; r++) {
            int f4 = r * 32 + lane;
            int h  = (f4 * 4) / C;
            float wgt = (h < 2) ? (h == 0 ? ex.x : ex.y)
                                : (h == 2 ? ex.z : ex.w);
            float4 v = fp[f4];
            acc[r].x += wgt * v.x; acc[r].y += wgt * v.y;
            acc[r].z += wgt * v.z; acc[r].w += wgt * v.w;
        }
    }

#pragma unroll
    for (int r = 0; r < NR; r++) {
        int f4 = r * 32 + lane;
        int h  = (f4 * 4) / C;
        float inv = (h < 2) ? (h == 0 ? i0 : i1)
                            : (h == 2 ? i2 : i3);
        acc[r].x *= inv; acc[r].y *= inv; acc[r].z *= inv; acc[r].w *= inv;
    }

    if (MODE == 2) {
        float4 t;
        t.x = acc[0].x + acc[1].x;
        t.y = acc[0].y + acc[1].y;
        t.z = acc[0].z + acc[1].z;
        t.w = acc[0].w + acc[1].w;
        t.x += __shfl_xor_sync(0xffffffffu, t.x, 16);
        t.y += __shfl_xor_sync(0xffffffffu, t.y, 16);
        t.z += __shfl_xor_sync(0xffffffffu, t.z, 16);
        t.w += __shfl_xor_sync(0xffffffffu, t.w, 16);
        if (lane < 16) {
            float4 bb = *(const float4*)(bias + (lane << 2));
            float4 y = make_float4(0.25f * t.x + bb.x, 0.25f * t.y + bb.y,
                                   0.25f * t.z + bb.z, 0.25f * t.w + bb.w);
            *(float4*)(xout + (size_t)w * 64 + (lane << 2)) = y;
        }
    } else {
        int f = lane << 2;
        float4 v = acc[0];
        float4 bb = *(const float4*)(bias + f);
        v.x += bb.x; v.y += bb.y; v.z += bb.z; v.w += bb.w;
        v.x = (v.x > 0.f) ? v.x : expm1f(v.x);
        v.y = (v.y > 0.f) ? v.y : expm1f(v.y);
        v.z = (v.z > 0.f) ? v.z : expm1f(v.z);
        v.w = (v.w > 0.f) ? v.w : expm1f(v.w);
        float s1 = v.x + v.y + v.z + v.w;
        float s2 = v.x * v.x + v.y * v.y + v.z * v.z + v.w * v.w;
#pragma unroll
        for (int o = 16; o; o >>= 1) {
            s1 += __shfl_xor_sync(0xffffffffu, s1, o);
            s2 += __shfl_xor_sync(0xffffffffu, s2, o);
        }
        float mu = s1 * (1.f / 128.f);
        float var = s2 * (1.f / 128.f) - mu * mu;
        float rinv = rsqrtf(var + 1e-5f);
        float4 wv = *(const float4*)(lnw + f);
        float4 bv = *(const float4*)(lnb + f);
        float4 y;
        y.x = (v.x - mu) * rinv * wv.x + bv.x;
        y.y = (v.y - mu) * rinv * wv.y + bv.y;
        y.z = (v.z - mu) * rinv * wv.z + bv.z;
        y.w = (v.w - mu) * rinv * wv.w + bv.w;
        if (MODE == 0) {
            float4 sk = *(const float4*)(skip + (size_t)w * 128 + f);
            float4 bs = *(const float4*)(bskip + f);
            y.x += sk.x + bs.x; y.y += sk.y + bs.y;
            y.z += sk.z + bs.z; y.w += sk.w + bs.w;
        }
        *(float4*)(xout + (size_t)w * 128 + f) = y;
    }
}

// ---------------------------------------------------------------------------
// Coalesced alpha output: alpha[e,h] = exp(leakyrelu(as[src]+ad[dst])) * inv[dst,h]
// ---------------------------------------------------------------------------
__global__ __launch_bounds__(256)
void alpha_kernel(const float* __restrict__ as_,
                  const float* __restrict__ ad_,
                  const float* __restrict__ inv_,
                  float* __restrict__ alpha, int E) {
    int i = blockIdx.x * blockDim.x + threadIdx.x;
    if (i >= E) return;
    int s = g_src[i], d = g_dst[i];
    float4 av  = *(const float4*)(as_ + 4 * (size_t)s);
    float4 adv = *(const float4*)(ad_ + 4 * (size_t)d);
    float4 iv  = *(const float4*)(inv_ + 4 * (size_t)d);
    float e0 = av.x + adv.x; e0 = (e0 > 0.f) ? e0 : 0.2f * e0;
    float e1 = av.y + adv.y; e1 = (e1 > 0.f) ? e1 : 0.2f * e1;
    float e2 = av.z + adv.z; e2 = (e2 > 0.f) ? e2 : 0.2f * e2;
    float e3 = av.w + adv.w; e3 = (e3 > 0.f) ? e3 : 0.2f * e3;
    float4 y = make_float4(__expf(e0) * iv.x, __expf(e1) * iv.y,
                           __expf(e2) * iv.z, __expf(e3) * iv.w);
    *(float4*)(alpha + (size_t)i * 4) = y;
}

// ---------------------------------------------------------------------------
// Host
// ---------------------------------------------------------------------------
extern "C" void kernel_launch(void* const* d_in, const int* in_sizes, int n_in,
                              void* d_out, int out_size) {
    const float* x      = (const float*)d_in[0];
    const void*  ei     = d_in[1];
    const float* W1     = (const float*)d_in[2];
    const float* a_src1 = (const float*)d_in[3];
    const float* a_dst1 = (const float*)d_in[4];
    const float* b1     = (const float*)d_in[5];
    const float* ln1_w  = (const float*)d_in[6];
    const float* ln1_b  = (const float*)d_in[7];
    const float* Wskip  = (const float*)d_in[8];
    const float* bskip  = (const float*)d_in[9];
    const float* W2     = (const float*)d_in[10];
    const float* a_src2 = (const float*)d_in[11];
    const float* a_dst2 = (const float*)d_in[12];
    const float* b2     = (const float*)d_in[13];
    const float* ln2_w  = (const float*)d_in[14];
    const float* ln2_b  = (const float*)d_in[15];
    const float* W3     = (const float*)d_in[16];
    const float* a_src3 = (const float*)d_in[17];
    const float* a_dst3 = (const float*)d_in[18];
    const float* b3     = (const float*)d_in[19];

    int N = in_sizes[0] / 128;
    int E = in_sizes[1] / 2;

    float* out    = (float*)d_out;
    float* alpha1 = out + (size_t)N * 64;
    float* alpha2 = alpha1 + (size_t)E * 4;
    float* alpha3 = alpha2 + (size_t)E * 4;

    float *feat, *skip, *xin, *as_, *ad_, *inv_;
    cudaGetSymbolAddress((void**)&feat, g_feat);
    cudaGetSymbolAddress((void**)&skip, g_skip);
    cudaGetSymbolAddress((void**)&xin,  g_xin);
    cudaGetSymbolAddress((void**)&as_,  g_as);
    cudaGetSymbolAddress((void**)&ad_,  g_ad);
    cudaGetSymbolAddress((void**)&inv_, g_inv);

    const int TB = 256;
    dim3 gemm_grid2(2, (N + 127) / 128);   // M=128 (2 x 64-col tiles)
    dim3 gemm_grid4(4, (N + 127) / 128);   // M=256
    int attn_blocks = (N * 4 * 32 + TB - 1) / TB;
    int edgeE_blocks = (E + TB - 1) / TB;
    int node_warp_blocks = (N * 32 + TB - 1) / TB;
    int zero_blocks = (N + TB - 1) / TB;
    int nb = (N + 1023) / 1024;

    // ---- CSR build (once; shared by all 3 layers) ----
    detect_idx_kernel<<<1, 32>>>((const long long*)ei, N);
    zero_deg_kernel<<<zero_blocks, TB>>>(N);
    convert_idx_kernel<<<edgeE_blocks, TB>>>(ei, E);
    scan1_kernel<<<nb, 1024>>>(N);
    scan2_kernel<<<1, 64>>>(nb);
    scan3_kernel<<<(N + 1 + TB - 1) / TB, TB>>>(N, nb);
    scatter_kernel<<<edgeE_blocks, TB>>>(E);

    // ---- Layer 1 ----
    gemm_tf32_kernel<<<gemm_grid2, TB>>>(x, W1, feat, N, 128, 128);
    gemm_tf32_kernel<<<gemm_grid2, TB>>>(x, Wskip, skip, N, 128, 128);
    attn_coef_kernel<<<attn_blocks, TB>>>(feat, a_src1, a_dst1, as_, ad_, N, 32);
    gat_edge_kernel<32, 0><<<node_warp_blocks, TB>>>(
        feat, as_, ad_, inv_, xin, b1, ln1_w, ln1_b, skip, bskip, N);
    alpha_kernel<<<edgeE_blocks, TB>>>(as_, ad_, inv_, alpha1, E);

    // ---- Layer 2 ----
    gemm_tf32_kernel<<<gemm_grid2, TB>>>(xin, W2, feat, N, 128, 128);
    attn_coef_kernel<<<attn_blocks, TB>>>(feat, a_src2, a_dst2, as_, ad_, N, 32);
    gat_edge_kernel<32, 1><<<node_warp_blocks, TB>>>(
        feat, as_, ad_, inv_, xin, b2, ln2_w, ln2_b, nullptr, nullptr, N);
    alpha_kernel<<<edgeE_blocks, TB>>>(as_, ad_, inv_, alpha2, E);

    // ---- Layer 3 ----
    gemm_tf32_kernel<<<gemm_grid4, TB>>>(xin, W3, feat, N, 128, 256);
    attn_coef_kernel<<<attn_blocks, TB>>>(feat, a_src3, a_dst3, as_, ad_, N, 64);
    gat_edge_kernel<64, 2><<<node_warp_blocks, TB>>>(
        feat, as_, ad_, inv_, out, b3, nullptr, nullptr, nullptr, nullptr, N);
    alpha_kernel<<<edgeE_blocks, TB>>>(as_, ad_, inv_, alpha3, E);
}

// round 16
// speedup vs baseline: 1.0197x; 1.0197x over previous
#include <cuda_runtime.h>
#include <cuda_bf16.h>
#include <math.h>
#include <stdint.h>

// ---------------------------------------------------------------------------
// GAT 3-layer fused pipeline for GB300 — round 13:
//   * revert to fp32 8x8 GEMM (TF32 regressed)
//   * layer-3 restructure: aggregate xin (not feat), stacked 512x64 GEMM,
//     reduced attention weights (no layer-3 feat at all)
// d_out layout (fp32): out[N*64] | alpha1[E*4] | alpha2[E*4] | alpha3[E*4]
// ---------------------------------------------------------------------------

#define MAX_N 50000
#define MAX_E 1600000

__device__ float g_feat[(size_t)MAX_N * 512];   // L1/L2: feat (N x 128); L3: u (N x 512)
__device__ float g_skip[(size_t)MAX_N * 128];
__device__ float g_xin [(size_t)MAX_N * 128];
__device__ float g_as  [(size_t)MAX_N * 4];
__device__ float g_ad  [(size_t)MAX_N * 4];
__device__ float g_inv [(size_t)MAX_N * 4];
__device__ float g_ex  [(size_t)MAX_E * 4];
__device__ int   g_src [MAX_E];
__device__ int   g_dst [MAX_E];
__device__ int   g_csr [MAX_E];
__device__ int   g_rowstart[MAX_N + 1];
__device__ int   g_deg   [MAX_N];
__device__ int   g_cursor[MAX_N];
__device__ int   g_scan  [MAX_N];
__device__ int   g_bsum  [64];
__device__ int   g_is64;
// layer-3 precomputed weights
__device__ float g_wstack[512 * 64];            // 0.25 * W3 restacked (512 x 64)
__device__ float g_was[128 * 4];                // [k][h]
__device__ float g_wad[128 * 4];

// ---------------------------------------------------------------------------
// Edge-index dtype sniffing + conversion to int32 (+ per-dst degree count)
// ---------------------------------------------------------------------------
__global__ void detect_idx_kernel(const long long* __restrict__ ei, int n_nodes) {
    if (threadIdx.x == 0 && blockIdx.x == 0) {
        int ok = 1;
        for (int i = 0; i < 16; i++) {
            long long v = ei[i];
            if (v < 0 || v >= (long long)n_nodes) { ok = 0; break; }
        }
        g_is64 = ok;
    }
}

__global__ void zero_deg_kernel(int n) {
    int i = blockIdx.x * blockDim.x + threadIdx.x;
    if (i < n) g_deg[i] = 0;
}

__global__ void convert_idx_kernel(const void* __restrict__ ei, int E) {
    int i = blockIdx.x * blockDim.x + threadIdx.x;
    if (i >= E) return;
    int s, d;
    if (g_is64) {
        const long long* p = (const long long*)ei;
        s = (int)p[i];
        d = (int)p[(size_t)E + i];
    } else {
        const int* p = (const int*)ei;
        s = p[i];
        d = p[E + i];
    }
    g_src[i] = s;
    g_dst[i] = d;
    atomicAdd(&g_deg[d], 1);
}

// ---------------------------------------------------------------------------
// Parallel 3-phase exclusive scan of g_deg -> g_rowstart / g_cursor
// ---------------------------------------------------------------------------
__global__ __launch_bounds__(1024)
void scan1_kernel(int n) {
    int i = blockIdx.x * 1024 + threadIdx.x;
    int lane = threadIdx.x & 31, wid = threadIdx.x >> 5;
    int v = (i < n) ? g_deg[i] : 0;
    int x = v;
#pragma unroll
    for (int o = 1; o < 32; o <<= 1) {
        int t = __shfl_up_sync(0xffffffffu, x, o);
        if (lane >= o) x += t;
    }
    __shared__ int ws[32];
    if (lane == 31) ws[wid] = x;
    __syncthreads();
    if (wid == 0) {
        int y = ws[lane];
#pragma unroll
        for (int o = 1; o < 32; o <<= 1) {
            int t = __shfl_up_sync(0xffffffffu, y, o);
            if (lane >= o) y += t;
        }
        ws[lane] = y;
    }
    __syncthreads();
    int incl = x + (wid ? ws[wid - 1] : 0);
    if (i < n) g_scan[i] = incl;
    if (threadIdx.x == 1023) g_bsum[blockIdx.x] = incl;
}

__global__ void scan2_kernel(int nb) {   // <<<1, 64>>>; nb <= 64
    int tid = threadIdx.x;
    int lane = tid & 31, wid = tid >> 5;
    int v = (tid < nb) ? g_bsum[tid] : 0;
    int x = v;
#pragma unroll
    for (int o = 1; o < 32; o <<= 1) {
        int t = __shfl_up_sync(0xffffffffu, x, o);
        if (lane >= o) x += t;
    }
    __shared__ int w0;
    if (wid == 0 && lane == 31) w0 = x;
    __syncthreads();
    if (wid == 1) x += w0;
    if (tid < nb) g_bsum[tid] = x;
}

__global__ void scan3_kernel(int n, int nb) {
    int i = blockIdx.x * blockDim.x + threadIdx.x;
    if (i > n) return;
    if (i == n) {
        g_rowstart[n] = g_bsum[nb - 1];
        return;
    }
    int blk = i >> 10;
    int excl = g_scan[i] - g_deg[i] + (blk ? g_bsum[blk - 1] : 0);
    g_rowstart[i] = excl;
    g_cursor[i]   = excl;
}

__global__ void scatter_kernel(int E) {
    int i = blockIdx.x * blockDim.x + threadIdx.x;
    if (i >= E) return;
    int d = g_dst[i];
    int pos = atomicAdd(&g_cursor[d], 1);
    g_csr[pos] = g_src[i];
}

// ---------------------------------------------------------------------------
// Layer-3 weight prep:
//   Wstack[h*128+k][c] = 0.25 * W3[k][h*64+c]
//   w_as[k][h] = sum_c W3[k][h*64+c] * a_src3[h*64+c]   (w_ad likewise)
// ---------------------------------------------------------------------------
__global__ void prep_w3_kernel(const float* __restrict__ W3,
                               const float* __restrict__ a_src3,
                               const float* __restrict__ a_dst3) {
    int i = blockIdx.x * blockDim.x + threadIdx.x;
    if (i < 512 * 64) {
        int r = i >> 6, c = i & 63;
        int h = r >> 7, k = r & 127;
        g_wstack[i] = 0.25f * W3[k * 256 + h * 64 + c];
    }
    if (i < 512) {
        int k = i >> 2, h = i & 3;
        float s1 = 0.f, s2 = 0.f;
        const float* wp = W3 + k * 256 + h * 64;
        const float* ap = a_src3 + h * 64;
        const float* dp = a_dst3 + h * 64;
        for (int c = 0; c < 64; c++) {
            float wv = wp[c];
            s1 += wv * ap[c];
            s2 += wv * dp[c];
        }
        g_was[i] = s1;
        g_wad[i] = s2;
    }
}

// ---------------------------------------------------------------------------
// Tiled fp32 GEMM: C[n,m] = sum_k A[n,k] * B[k,m]
// BM=128, BN=128, BK=16, 256 threads, 8x8 per thread (4+4 split tiles).
// ---------------------------------------------------------------------------
__global__ __launch_bounds__(256)
void gemm_kernel(const float* __restrict__ A, const float* __restrict__ B,
                 float* __restrict__ C, int nRows, int K, int M) {
    __shared__ float As[16][136];
    __shared__ float Bs[16][128];

    int tid = threadIdx.x;
    int tx = tid & 15, ty = tid >> 4;
    int row0 = blockIdx.y * 128, col0 = blockIdx.x * 128;

    float acc[8][8];
#pragma unroll
    for (int i = 0; i < 8; i++)
#pragma unroll
        for (int j = 0; j < 8; j++) acc[i][j] = 0.f;

    for (int k0 = 0; k0 < K; k0 += 16) {
#pragma unroll
        for (int t = 0; t < 2; t++) {
            int f = tid + t * 256;
            int ar = f >> 2;
            int ac = (f & 3) << 2;
            int grow = row0 + ar;
            float4 v = make_float4(0.f, 0.f, 0.f, 0.f);
            if (grow < nRows)
                v = *(const float4*)(A + (size_t)grow * K + k0 + ac);
            As[ac + 0][ar] = v.x; As[ac + 1][ar] = v.y;
            As[ac + 2][ar] = v.z; As[ac + 3][ar] = v.w;
        }
#pragma unroll
        for (int t = 0; t < 2; t++) {
            int f = tid + t * 256;
            int br = f >> 5;
            int bc = (f & 31) << 2;
            *(float4*)&Bs[br][bc] =
                *(const float4*)(B + (size_t)(k0 + br) * M + col0 + bc);
        }
        __syncthreads();
#pragma unroll
        for (int k = 0; k < 16; k++) {
            float4 a0 = *(const float4*)&As[k][ty << 2];
            float4 a1 = *(const float4*)&As[k][64 + (ty << 2)];
            float4 b0 = *(const float4*)&Bs[k][tx << 2];
            float4 b1 = *(const float4*)&Bs[k][64 + (tx << 2)];
            float a[8] = {a0.x, a0.y, a0.z, a0.w, a1.x, a1.y, a1.z, a1.w};
            float b[8] = {b0.x, b0.y, b0.z, b0.w, b1.x, b1.y, b1.z, b1.w};
#pragma unroll
            for (int i = 0; i < 8; i++)
#pragma unroll
                for (int j = 0; j < 8; j++)
                    acc[i][j] += a[i] * b[j];
        }
        __syncthreads();
    }
#pragma unroll
    for (int i = 0; i < 8; i++) {
        int row = row0 + ((i < 4) ? ((ty << 2) + i) : (64 + (ty << 2) + i - 4));
        if (row >= nRows) continue;
        float* cp = C + (size_t)row * M + col0;
        *(float4*)(cp + (tx << 2)) =
            make_float4(acc[i][0], acc[i][1], acc[i][2], acc[i][3]);
        *(float4*)(cp + 64 + (tx << 2)) =
            make_float4(acc[i][4], acc[i][5], acc[i][6], acc[i][7]);
    }
}

// ---------------------------------------------------------------------------
// gemm64: out[n,c] = sum_k u[n,k] * Wstack[k,c] + b3[c]
// BM=128, BN=64 (=M), BK=16, 256 threads, 8x4 per thread. K=512.
// ---------------------------------------------------------------------------
__global__ __launch_bounds__(256)
void gemm64_kernel(const float* __restrict__ A, const float* __restrict__ B,
                   const float* __restrict__ bias, float* __restrict__ C,
                   int nRows) {
    const int K = 512, M = 64;
    __shared__ float As[16][136];
    __shared__ float Bs[16][64];

    int tid = threadIdx.x;
    int tx = tid & 15, ty = tid >> 4;
    int row0 = blockIdx.x * 128;

    float acc[8][4];
#pragma unroll
    for (int i = 0; i < 8; i++)
#pragma unroll
        for (int j = 0; j < 4; j++) acc[i][j] = 0.f;

    for (int k0 = 0; k0 < K; k0 += 16) {
#pragma unroll
        for (int t = 0; t < 2; t++) {
            int f = tid + t * 256;
            int ar = f >> 2;
            int ac = (f & 3) << 2;
            int grow = row0 + ar;
            float4 v = make_float4(0.f, 0.f, 0.f, 0.f);
            if (grow < nRows)
                v = *(const float4*)(A + (size_t)grow * K + k0 + ac);
            As[ac + 0][ar] = v.x; As[ac + 1][ar] = v.y;
            As[ac + 2][ar] = v.z; As[ac + 3][ar] = v.w;
        }
        {
            int br = tid >> 4;           // 0..15
            int bc = (tid & 15) << 2;    // 0..60
            *(float4*)&Bs[br][bc] =
                *(const float4*)(B + (size_t)(k0 + br) * M + bc);
        }
        __syncthreads();
#pragma unroll
        for (int k = 0; k < 16; k++) {
            float4 a0 = *(const float4*)&As[k][ty << 2];
            float4 a1 = *(const float4*)&As[k][64 + (ty << 2)];
            float4 b0 = *(const float4*)&Bs[k][tx << 2];
            float a[8] = {a0.x, a0.y, a0.z, a0.w, a1.x, a1.y, a1.z, a1.w};
#pragma unroll
            for (int i = 0; i < 8; i++) {
                acc[i][0] += a[i] * b0.x;
                acc[i][1] += a[i] * b0.y;
                acc[i][2] += a[i] * b0.z;
                acc[i][3] += a[i] * b0.w;
            }
        }
        __syncthreads();
    }
    float4 bb = *(const float4*)(bias + (tx << 2));
#pragma unroll
    for (int i = 0; i < 8; i++) {
        int row = row0 + ((i < 4) ? ((ty << 2) + i) : (64 + (ty << 2) + i - 4));
        if (row >= nRows) continue;
        *(float4*)(C + (size_t)row * M + (tx << 2)) =
            make_float4(acc[i][0] + bb.x, acc[i][1] + bb.y,
                        acc[i][2] + bb.z, acc[i][3] + bb.w);
    }
}

// ---------------------------------------------------------------------------
// as_[n,h] = sum_c h[n,h,c]*a_src[h,c]; ad_ likewise. One warp per (n,h).
// (layers 1/2, feat-based)
// ---------------------------------------------------------------------------
__global__ __launch_bounds__(256)
void attn_coef_kernel(const float* __restrict__ feat,
                      const float* __restrict__ a_src, const float* __restrict__ a_dst,
                      float* __restrict__ as_, float* __restrict__ ad_,
                      int n, int C) {
    int w = (blockIdx.x * blockDim.x + threadIdx.x) >> 5;
    int lane = threadIdx.x & 31;
    if (w >= n * 4) return;
    int node = w >> 2, h = w & 3;
    const float* fp = feat + (size_t)node * 4 * C + h * C;
    float s1 = 0.f, s2 = 0.f;
    for (int c = lane; c < C; c += 32) {
        float v = fp[c];
        s1 += v * a_src[h * C + c];
        s2 += v * a_dst[h * C + c];
    }
#pragma unroll
    for (int o = 16; o; o >>= 1) {
        s1 += __shfl_xor_sync(0xffffffffu, s1, o);
        s2 += __shfl_xor_sync(0xffffffffu, s2, o);
    }
    if (lane == 0) { as_[w] = s1; ad_[w] = s2; }
}

// ---------------------------------------------------------------------------
// Layer-3 attention coefficients from xin via reduced weights:
//   as[n,h] = sum_k xin[n,k] * w_as[k,h]. One warp per node.
// ---------------------------------------------------------------------------
__global__ __launch_bounds__(256)
void attn3_kernel(const float* __restrict__ xin,
                  float* __restrict__ as_, float* __restrict__ ad_, int n) {
    int w = (blockIdx.x * blockDim.x + threadIdx.x) >> 5;
    int lane = threadIdx.x & 31;
    if (w >= n) return;
    float4 xv = *(const float4*)(xin + (size_t)w * 128 + (lane << 2));
    float s0 = 0.f, s1 = 0.f, s2 = 0.f, s3 = 0.f;
    float t0 = 0.f, t1 = 0.f, t2 = 0.f, t3 = 0.f;
#pragma unroll
    for (int j = 0; j < 4; j++) {
        int k = (lane << 2) + j;
        float xk = (j == 0) ? xv.x : (j == 1) ? xv.y : (j == 2) ? xv.z : xv.w;
        float4 wa = *(const float4*)(g_was + k * 4);
        float4 wd = *(const float4*)(g_wad + k * 4);
        s0 += xk * wa.x; s1 += xk * wa.y; s2 += xk * wa.z; s3 += xk * wa.w;
        t0 += xk * wd.x; t1 += xk * wd.y; t2 += xk * wd.z; t3 += xk * wd.w;
    }
#pragma unroll
    for (int o = 16; o; o >>= 1) {
        s0 += __shfl_xor_sync(0xffffffffu, s0, o);
        s1 += __shfl_xor_sync(0xffffffffu, s1, o);
        s2 += __shfl_xor_sync(0xffffffffu, s2, o);
        s3 += __shfl_xor_sync(0xffffffffu, s3, o);
        t0 += __shfl_xor_sync(0xffffffffu, t0, o);
        t1 += __shfl_xor_sync(0xffffffffu, t1, o);
        t2 += __shfl_xor_sync(0xffffffffu, t2, o);
        t3 += __shfl_xor_sync(0xffffffffu, t3, o);
    }
    if (lane == 0) {
        *(float4*)(as_ + 4 * (size_t)w) = make_float4(s0, s1, s2, s3);
        *(float4*)(ad_ + 4 * (size_t)w) = make_float4(t0, t1, t2, t3);
    }
}

// ---------------------------------------------------------------------------
// Fused per-destination edge kernel, layers 1/2 (warp per dst), atomic-free.
//   MODE 0: bias+ELU+LN+skip -> xout;  MODE 1: bias+ELU+LN -> xout
// ---------------------------------------------------------------------------
template <int MODE>
__global__ __launch_bounds__(256)
void gat_edge_kernel(const float* __restrict__ feat,
                     const float* __restrict__ as_,
                     const float* __restrict__ ad_,
                     float* __restrict__ inv_out,
                     float* __restrict__ xout,
                     const float* __restrict__ bias,
                     const float* __restrict__ lnw,
                     const float* __restrict__ lnb,
                     const float* __restrict__ skip,
                     const float* __restrict__ bskip,
                     int n) {
    int w = (blockIdx.x * blockDim.x + threadIdx.x) >> 5;
    int lane = threadIdx.x & 31;
    if (w >= n) return;
    int start = g_rowstart[w];
    int end   = g_rowstart[w + 1];

    float4 adv = *(const float4*)(ad_ + 4 * (size_t)w);

    // ---- Loop A: ex + denominator partials ----
    float d0 = 0.f, d1 = 0.f, d2 = 0.f, d3 = 0.f;
    for (int i = start + lane; i < end; i += 32) {
        int sidx = g_csr[i];
        float4 av = *(const float4*)(as_ + 4 * (size_t)sidx);
        float e0 = av.x + adv.x; e0 = (e0 > 0.f) ? e0 : 0.2f * e0;
        float e1 = av.y + adv.y; e1 = (e1 > 0.f) ? e1 : 0.2f * e1;
        float e2 = av.z + adv.z; e2 = (e2 > 0.f) ? e2 : 0.2f * e2;
        float e3 = av.w + adv.w; e3 = (e3 > 0.f) ? e3 : 0.2f * e3;
        float x0 = __expf(e0), x1 = __expf(e1), x2 = __expf(e2), x3 = __expf(e3);
        *(float4*)(g_ex + (size_t)i * 4) = make_float4(x0, x1, x2, x3);
        d0 += x0; d1 += x1; d2 += x2; d3 += x3;
    }
    __syncwarp();
#pragma unroll
    for (int o = 16; o; o >>= 1) {
        d0 += __shfl_xor_sync(0xffffffffu, d0, o);
        d1 += __shfl_xor_sync(0xffffffffu, d1, o);
        d2 += __shfl_xor_sync(0xffffffffu, d2, o);
        d3 += __shfl_xor_sync(0xffffffffu, d3, o);
    }
    float i0 = 1.f / (d0 + 1e-16f);
    float i1 = 1.f / (d1 + 1e-16f);
    float i2 = 1.f / (d2 + 1e-16f);
    float i3 = 1.f / (d3 + 1e-16f);
    if (lane == 0)
        *(float4*)(inv_out + 4 * (size_t)w) = make_float4(i0, i1, i2, i3);

    // ---- Loop C: register-accumulated aggregation (feat rows, 128 wide) ----
    float4 acc = make_float4(0.f, 0.f, 0.f, 0.f);
    int h = lane >> 3;      // 4 consecutive floats per lane; 8 lanes per head
    float inv = (h < 2) ? (h == 0 ? i0 : i1) : (h == 2 ? i2 : i3);

#pragma unroll 2
    for (int i = start; i < end; i++) {
        int sidx = g_csr[i];
        float4 ex = *(const float4*)(g_ex + (size_t)i * 4);
        float wgt = (h < 2) ? (h == 0 ? ex.x : ex.y) : (h == 2 ? ex.z : ex.w);
        float4 v = *(const float4*)(feat + (size_t)sidx * 128 + (lane << 2));
        acc.x += wgt * v.x; acc.y += wgt * v.y;
        acc.z += wgt * v.z; acc.w += wgt * v.w;
    }
    acc.x *= inv; acc.y *= inv; acc.z *= inv; acc.w *= inv;

    // ---- epilogue: bias + ELU + LayerNorm(128) [+ skip] ----
    int f = lane << 2;
    float4 v = acc;
    float4 bb = *(const float4*)(bias + f);
    v.x += bb.x; v.y += bb.y; v.z += bb.z; v.w += bb.w;
    v.x = (v.x > 0.f) ? v.x : expm1f(v.x);
    v.y = (v.y > 0.f) ? v.y : expm1f(v.y);
    v.z = (v.z > 0.f) ? v.z : expm1f(v.z);
    v.w = (v.w > 0.f) ? v.w : expm1f(v.w);
    float s1 = v.x + v.y + v.z + v.w;
    float s2 = v.x * v.x + v.y * v.y + v.z * v.z + v.w * v.w;
#pragma unroll
    for (int o = 16; o; o >>= 1) {
        s1 += __shfl_xor_sync(0xffffffffu, s1, o);
        s2 += __shfl_xor_sync(0xffffffffu, s2, o);
    }
    float mu = s1 * (1.f / 128.f);
    float var = s2 * (1.f / 128.f) - mu * mu;
    float rinv = rsqrtf(var + 1e-5f);
    float4 wv = *(const float4*)(lnw + f);
    float4 bv = *(const float4*)(lnb + f);
    float4 y;
    y.x = (v.x - mu) * rinv * wv.x + bv.x;
    y.y = (v.y - mu) * rinv * wv.y + bv.y;
    y.z = (v.z - mu) * rinv * wv.z + bv.z;
    y.w = (v.w - mu) * rinv * wv.w + bv.w;
    if (MODE == 0) {
        float4 sk = *(const float4*)(skip + (size_t)w * 128 + f);
        float4 bs = *(const float4*)(bskip + f);
        y.x += sk.x + bs.x; y.y += sk.y + bs.y;
        y.z += sk.z + bs.z; y.w += sk.w + bs.w;
    }
    *(float4*)(xout + (size_t)w * 128 + f) = y;
}

// ---------------------------------------------------------------------------
// Layer-3 edge kernel: gathers xin[src] (512B/edge) into 4 per-head
// z-accumulators; u[n, h*128 + f] = inv_h * z_h[f].
// ---------------------------------------------------------------------------
__global__ __launch_bounds__(256)
void gat_edge3_kernel(const float* __restrict__ xin,
                      const float* __restrict__ as_,
                      const float* __restrict__ ad_,
                      float* __restrict__ inv_out,
                      float* __restrict__ u,
                      int n) {
    int w = (blockIdx.x * blockDim.x + threadIdx.x) >> 5;
    int lane = threadIdx.x & 31;
    if (w >= n) return;
    int start = g_rowstart[w];
    int end   = g_rowstart[w + 1];

    float4 adv = *(const float4*)(ad_ + 4 * (size_t)w);

    // ---- Loop A ----
    float d0 = 0.f, d1 = 0.f, d2 = 0.f, d3 = 0.f;
    for (int i = start + lane; i < end; i += 32) {
        int sidx = g_csr[i];
        float4 av = *(const float4*)(as_ + 4 * (size_t)sidx);
        float e0 = av.x + adv.x; e0 = (e0 > 0.f) ? e0 : 0.2f * e0;
        float e1 = av.y + adv.y; e1 = (e1 > 0.f) ? e1 : 0.2f * e1;
        float e2 = av.z + adv.z; e2 = (e2 > 0.f) ? e2 : 0.2f * e2;
        float e3 = av.w + adv.w; e3 = (e3 > 0.f) ? e3 : 0.2f * e3;
        float x0 = __expf(e0), x1 = __expf(e1), x2 = __expf(e2), x3 = __expf(e3);
        *(float4*)(g_ex + (size_t)i * 4) = make_float4(x0, x1, x2, x3);
        d0 += x0; d1 += x1; d2 += x2; d3 += x3;
    }
    __syncwarp();
#pragma unroll
    for (int o = 16; o; o >>= 1) {
        d0 += __shfl_xor_sync(0xffffffffu, d0, o);
        d1 += __shfl_xor_sync(0xffffffffu, d1, o);
        d2 += __shfl_xor_sync(0xffffffffu, d2, o);
        d3 += __shfl_xor_sync(0xffffffffu, d3, o);
    }
    float i0 = 1.f / (d0 + 1e-16f);
    float i1 = 1.f / (d1 + 1e-16f);
    float i2 = 1.f / (d2 + 1e-16f);
    float i3 = 1.f / (d3 + 1e-16f);
    if (lane == 0)
        *(float4*)(inv_out + 4 * (size_t)w) = make_float4(i0, i1, i2, i3);

    // ---- Loop C: z_h = sum ex_h * xin[src]  (4 accumulators/lane) ----
    float4 a0 = make_float4(0.f, 0.f, 0.f, 0.f);
    float4 a1 = a0, a2 = a0, a3 = a0;
#pragma unroll 2
    for (int i = start; i < end; i++) {
        int sidx = g_csr[i];
        float4 ex = *(const float4*)(g_ex + (size_t)i * 4);
        float4 v = *(const float4*)(xin + (size_t)sidx * 128 + (lane << 2));
        a0.x += ex.x * v.x; a0.y += ex.x * v.y; a0.z += ex.x * v.z; a0.w += ex.x * v.w;
        a1.x += ex.y * v.x; a1.y += ex.y * v.y; a1.z += ex.y * v.z; a1.w += ex.y * v.w;
        a2.x += ex.z * v.x; a2.y += ex.z * v.y; a2.z += ex.z * v.z; a2.w += ex.z * v.w;
        a3.x += ex.w * v.x; a3.y += ex.w * v.y; a3.z += ex.w * v.z; a3.w += ex.w * v.w;
    }
    a0.x *= i0; a0.y *= i0; a0.z *= i0; a0.w *= i0;
    a1.x *= i1; a1.y *= i1; a1.z *= i1; a1.w *= i1;
    a2.x *= i2; a2.y *= i2; a2.z *= i2; a2.w *= i2;
    a3.x *= i3; a3.y *= i3; a3.z *= i3; a3.w *= i3;

    float* up = u + (size_t)w * 512 + (lane << 2);
    *(float4*)(up +   0) = a0;
    *(float4*)(up + 128) = a1;
    *(float4*)(up + 256) = a2;
    *(float4*)(up + 384) = a3;
}

// ---------------------------------------------------------------------------
// Coalesced alpha output
// ---------------------------------------------------------------------------
__global__ __launch_bounds__(256)
void alpha_kernel(const float* __restrict__ as_,
                  const float* __restrict__ ad_,
                  const float* __restrict__ inv_,
                  float* __restrict__ alpha, int E) {
    int i = blockIdx.x * blockDim.x + threadIdx.x;
    if (i >= E) return;
    int s = g_src[i], d = g_dst[i];
    float4 av  = *(const float4*)(as_ + 4 * (size_t)s);
    float4 adv = *(const float4*)(ad_ + 4 * (size_t)d);
    float4 iv  = *(const float4*)(inv_ + 4 * (size_t)d);
    float e0 = av.x + adv.x; e0 = (e0 > 0.f) ? e0 : 0.2f * e0;
    float e1 = av.y + adv.y; e1 = (e1 > 0.f) ? e1 : 0.2f * e1;
    float e2 = av.z + adv.z; e2 = (e2 > 0.f) ? e2 : 0.2f * e2;
    float e3 = av.w + adv.w; e3 = (e3 > 0.f) ? e3 : 0.2f * e3;
    float4 y = make_float4(__expf(e0) * iv.x, __expf(e1) * iv.y,
                           __expf(e2) * iv.z, __expf(e3) * iv.w);
    *(float4*)(alpha + (size_t)i * 4) = y;
}

// ---------------------------------------------------------------------------
// Host
// ---------------------------------------------------------------------------
extern "C" void kernel_launch(void* const* d_in, const int* in_sizes, int n_in,
                              void* d_out, int out_size) {
    const float* x      = (const float*)d_in[0];
    const void*  ei     = d_in[1];
    const float* W1     = (const float*)d_in[2];
    const float* a_src1 = (const float*)d_in[3];
    const float* a_dst1 = (const float*)d_in[4];
    const float* b1     = (const float*)d_in[5];
    const float* ln1_w  = (const float*)d_in[6];
    const float* ln1_b  = (const float*)d_in[7];
    const float* Wskip  = (const float*)d_in[8];
    const float* bskip  = (const float*)d_in[9];
    const float* W2     = (const float*)d_in[10];
    const float* a_src2 = (const float*)d_in[11];
    const float* a_dst2 = (const float*)d_in[12];
    const float* b2     = (const float*)d_in[13];
    const float* ln2_w  = (const float*)d_in[14];
    const float* ln2_b  = (const float*)d_in[15];
    const float* W3     = (const float*)d_in[16];
    const float* a_src3 = (const float*)d_in[17];
    const float* a_dst3 = (const float*)d_in[18];
    const float* b3     = (const float*)d_in[19];

    int N = in_sizes[0] / 128;
    int E = in_sizes[1] / 2;

    float* out    = (float*)d_out;
    float* alpha1 = out + (size_t)N * 64;
    float* alpha2 = alpha1 + (size_t)E * 4;
    float* alpha3 = alpha2 + (size_t)E * 4;

    float *feat, *skip, *xin, *as_, *ad_, *inv_, *wstack;
    cudaGetSymbolAddress((void**)&feat, g_feat);
    cudaGetSymbolAddress((void**)&skip, g_skip);
    cudaGetSymbolAddress((void**)&xin,  g_xin);
    cudaGetSymbolAddress((void**)&as_,  g_as);
    cudaGetSymbolAddress((void**)&ad_,  g_ad);
    cudaGetSymbolAddress((void**)&inv_, g_inv);
    cudaGetSymbolAddress((void**)&wstack, g_wstack);

    const int TB = 256;
    dim3 gemm_grid1(1, (N + 127) / 128);   // M=128
    int attn_blocks = (N * 4 * 32 + TB - 1) / TB;
    int edgeE_blocks = (E + TB - 1) / TB;
    int node_warp_blocks = (N * 32 + TB - 1) / TB;
    int zero_blocks = (N + TB - 1) / TB;
    int nb = (N + 1023) / 1024;

    // ---- CSR build + layer-3 weight prep ----
    detect_idx_kernel<<<1, 32>>>((const long long*)ei, N);
    zero_deg_kernel<<<zero_blocks, TB>>>(N);
    convert_idx_kernel<<<edgeE_blocks, TB>>>(ei, E);
    scan1_kernel<<<nb, 1024>>>(N);
    scan2_kernel<<<1, 64>>>(nb);
    scan3_kernel<<<(N + 1 + TB - 1) / TB, TB>>>(N, nb);
    scatter_kernel<<<edgeE_blocks, TB>>>(E);
    prep_w3_kernel<<<(512 * 64 + TB - 1) / TB, TB>>>(W3, a_src3, a_dst3);

    // ---- Layer 1 ----
    gemm_kernel<<<gemm_grid1, TB>>>(x, W1, feat, N, 128, 128);
    gemm_kernel<<<gemm_grid1, TB>>>(x, Wskip, skip, N, 128, 128);
    attn_coef_kernel<<<attn_blocks, TB>>>(feat, a_src1, a_dst1, as_, ad_, N, 32);
    gat_edge_kernel<0><<<node_warp_blocks, TB>>>(
        feat, as_, ad_, inv_, xin, b1, ln1_w, ln1_b, skip, bskip, N);
    alpha_kernel<<<edgeE_blocks, TB>>>(as_, ad_, inv_, alpha1, E);

    // ---- Layer 2 ----
    gemm_kernel<<<gemm_grid1, TB>>>(xin, W2, feat, N, 128, 128);
    attn_coef_kernel<<<attn_blocks, TB>>>(feat, a_src2, a_dst2, as_, ad_, N, 32);
    gat_edge_kernel<1><<<node_warp_blocks, TB>>>(
        feat, as_, ad_, inv_, xin, b2, ln2_w, ln2_b, nullptr, nullptr, N);
    alpha_kernel<<<edgeE_blocks, TB>>>(as_, ad_, inv_, alpha2, E);

    // ---- Layer 3 (restructured: aggregate xin, then stacked GEMM) ----
    attn3_kernel<<<node_warp_blocks, TB>>>(xin, as_, ad_, N);
    gat_edge3_kernel<<<node_warp_blocks, TB>>>(xin, as_, ad_, inv_, feat, N);
    gemm64_kernel<<<(N + 127) / 128, TB>>>(feat, wstack, b3, out, N);
    alpha_kernel<<<edgeE_blocks, TB>>>(as_, ad_, inv_, alpha3, E);
}